// round 17
// baseline (speedup 1.0000x reference)
#include <cuda_runtime.h>
#include <cuda_fp16.h>
#include <cstdint>

// SAGE_68281390072709 — 2-layer GraphSAGE, fp32 I/O.
// Both layers: pure-fp16 cp.async tensor GEMM (x and weights pre-converted).
// Bucket aggregation; gather0 = 2 nodes/warp, 16 lanes/node, LDG.128 rows.

#define NN 50000
#define EE 800000
#define F0 128
#define F1 128
#define NC 41
#define CAP 80   // max in-degree; P(Poisson(16) >= 80) ~ 1e-28

__device__ __half    g_xh[NN * F0];      // x converted to fp16
__device__ __half    g_Y0h[NN * F1];
__device__ __half    g_S0h[NN * F1];     // self term, fp16
__device__ __half    g_hh[NN * F1];      // h after relu, fp16
__device__ __half    g_Y1h[NN * NC];
__device__ int       g_cnt[NN];          // zero at entry (gather1 restores)
__device__ int       g_bucket[NN * CAP];
__device__ uint32_t  g_W0s[64 * 128];    // W_self0 fp16 k-pair interleaved [K/2][128]
__device__ uint32_t  g_W0n[64 * 128];    // W_neigh0 likewise
__device__ uint32_t  g_W1s[64 * 64];     // W_self1 fp16 k-pair interleaved [K/2][64]
__device__ uint32_t  g_W1n[64 * 64];     // W_neigh1 likewise

// ---------------------------------------------------------------------------
__device__ __forceinline__ uint32_t pack_h2(float lo, float hi) {
    __half2 h = __floats2half2_rn(lo, hi);
    return *reinterpret_cast<uint32_t*>(&h);
}

__device__ __forceinline__ void mma_f16(float* c, const uint32_t* a, const uint32_t* b) {
    asm volatile(
        "mma.sync.aligned.m16n8k16.row.col.f32.f16.f16.f32 "
        "{%0,%1,%2,%3}, {%4,%5,%6,%7}, {%8,%9}, {%0,%1,%2,%3};"
        : "+f"(c[0]), "+f"(c[1]), "+f"(c[2]), "+f"(c[3])
        : "r"(a[0]), "r"(a[1]), "r"(a[2]), "r"(a[3]), "r"(b[0]), "r"(b[1]));
}

__device__ __forceinline__ void cp_async16(void* sdst, const void* gsrc, bool valid) {
    uint32_t s = (uint32_t)__cvta_generic_to_shared(sdst);
    int sz = valid ? 16 : 0;
    asm volatile("cp.async.cg.shared.global [%0], [%1], 16, %2;"
                 :: "r"(s), "l"(gsrc), "r"(sz));
}
#define CP_COMMIT() asm volatile("cp.async.commit_group;")

// ---------------------------------------------------------------------------
// bucket fill: one atomic pass over edges (2 edges/thread)
// ---------------------------------------------------------------------------
__global__ void fill_kernel(const int* __restrict__ src,
                            const int* __restrict__ dst, int E) {
    int i = (blockIdx.x * blockDim.x + threadIdx.x) * 2;
    if (i + 1 < E) {
        int2 s2 = *reinterpret_cast<const int2*>(src + i);
        int2 d2 = *reinterpret_cast<const int2*>(dst + i);
        int p0 = atomicAdd(&g_cnt[d2.x], 1);
        if (p0 < CAP) g_bucket[(long)d2.x * CAP + p0] = s2.x;
        int p1 = atomicAdd(&g_cnt[d2.y], 1);
        if (p1 < CAP) g_bucket[(long)d2.y * CAP + p1] = s2.y;
    } else if (i < E) {
        int d = dst[i];
        int pos = atomicAdd(&g_cnt[d], 1);
        if (pos < CAP) g_bucket[(long)d * CAP + pos] = src[i];
    }
}

// ---------------------------------------------------------------------------
// x -> fp16 (8 elements per thread); NN*F0 = 6.4M, exactly 3125 blocks x 256.
// ---------------------------------------------------------------------------
__global__ void cvt_x_kernel(const float* __restrict__ x) {
    long base = ((long)blockIdx.x * blockDim.x + threadIdx.x) * 8;
    float4 v0 = *reinterpret_cast<const float4*>(x + base);
    float4 v1 = *reinterpret_cast<const float4*>(x + base + 4);
    uint4 o;
    o.x = pack_h2(v0.x, v0.y);
    o.y = pack_h2(v0.z, v0.w);
    o.z = pack_h2(v1.x, v1.y);
    o.w = pack_h2(v1.z, v1.w);
    *reinterpret_cast<uint4*>(g_xh + base) = o;
}

// ---------------------------------------------------------------------------
// weight prep: both layers -> fp16 k-pair interleaved.
//   W0: [128,128] -> [64][128];  W1: [128,41] -> [64][64] zero-padded
// ---------------------------------------------------------------------------
__global__ void cvt_w_kernel(const float* __restrict__ W0s_,
                             const float* __restrict__ W0n_,
                             const float* __restrict__ W1s_,
                             const float* __restrict__ W1n_) {
    int i = blockIdx.x * blockDim.x + threadIdx.x;
    if (i < 64 * 128) {
        int q = i >> 7, n = i & 127;
        g_W0s[i] = pack_h2(W0s_[(2 * q) * 128 + n], W0s_[(2 * q + 1) * 128 + n]);
        g_W0n[i] = pack_h2(W0n_[(2 * q) * 128 + n], W0n_[(2 * q + 1) * 128 + n]);
    }
    if (i < 64 * 64) {
        int q = i >> 6, n = i & 63;
        float s0 = 0.f, s1 = 0.f, w0 = 0.f, w1 = 0.f;
        if (n < NC) {
            s0 = W1s_[(2 * q) * NC + n];
            s1 = W1s_[(2 * q + 1) * NC + n];
            w0 = W1n_[(2 * q) * NC + n];
            w1 = W1n_[(2 * q + 1) * NC + n];
        }
        g_W1s[i] = pack_h2(s0, s1);
        g_W1n[i] = pack_h2(w0, w1);
    }
}

// ---------------------------------------------------------------------------
// generic pure-fp16 cp.async GEMM:
//   C = A @ B, A fp16 [M,128], B packed uint32 [64][ldbq] (k-pair interleaved)
//   blockIdx.z selects (B0,C0) vs (B1,C1); blockIdx.y = 64-wide n tile.
// MODE 0: both outputs fp16, no N guard (N multiple of 64)
// MODE 1: C0 fp32 / C1 fp16, N guarded (layer 1, N=41)
// BM=128, BK=32, KT=4, 256 threads, double-buffered.
// ---------------------------------------------------------------------------
template <int MODE>
__global__ void __launch_bounds__(256)
hgemm_f16_kernel(const __half* __restrict__ A,
                 const uint32_t* __restrict__ B0q,
                 const uint32_t* __restrict__ B1q,
                 void* __restrict__ C0,
                 void* __restrict__ C1,
                 int M, int N, int ldbq) {
    constexpr int K = 128, BM = 128, BK = 32, KT = K / BK;  // 4
    __shared__ __align__(16) uint32_t As[2][BM][BK / 2 + 4];   // stride 20
    __shared__ __align__(16) uint32_t Bs[2][BK / 2][64 + 8];   // stride 72

    const int tid = threadIdx.x;
    const int lane = tid & 31;
    const int wid = tid >> 5;
    const int g = lane >> 2;
    const int t = lane & 3;
    const int wm = (wid >> 1) * 32;
    const int wn = (wid & 1) * 32;
    const int m0 = blockIdx.x * BM;
    const int n0 = blockIdx.y * 64;
    const uint32_t* Bq = (blockIdx.z == 0) ? B0q : B1q;

    float acc[2][4][4];
#pragma unroll
    for (int mf = 0; mf < 2; mf++)
#pragma unroll
        for (int nf = 0; nf < 4; nf++)
#pragma unroll
            for (int i = 0; i < 4; i++) acc[mf][nf][i] = 0.f;

    const int b_row = tid >> 4;      // 0..15
    const int b_c4 = (tid & 15) * 4; // 0..60

    auto load_tile = [&](int kt, int buf) {
#pragma unroll
        for (int i = 0; i < 2; i++) {
            int ch = tid + i * 256;
            int row = ch >> 2;
            int c4 = (ch & 3) * 4;
            int gm = m0 + row;
            cp_async16(&As[buf][row][c4],
                       A + (long)gm * K + kt * BK + c4 * 2, gm < M);
        }
        cp_async16(&Bs[buf][b_row][b_c4],
                   Bq + (long)(kt * 16 + b_row) * ldbq + n0 + b_c4, true);
    };

    load_tile(0, 0);
    CP_COMMIT();

    for (int kt = 0; kt < KT; kt++) {
        int buf = kt & 1;
        if (kt + 1 < KT) {
            load_tile(kt + 1, buf ^ 1);
            CP_COMMIT();
            asm volatile("cp.async.wait_group 1;");
        } else {
            asm volatile("cp.async.wait_group 0;");
        }
        __syncthreads();

#pragma unroll
        for (int ks2 = 0; ks2 < BK / 2; ks2 += 8) {
            uint32_t a[2][4], b[4][2];
#pragma unroll
            for (int mf = 0; mf < 2; mf++) {
                int r = wm + mf * 16;
                a[mf][0] = As[buf][r + g][ks2 + t];
                a[mf][1] = As[buf][r + g + 8][ks2 + t];
                a[mf][2] = As[buf][r + g][ks2 + t + 4];
                a[mf][3] = As[buf][r + g + 8][ks2 + t + 4];
            }
#pragma unroll
            for (int nf = 0; nf < 4; nf++) {
                int c = wn + nf * 8 + g;
                b[nf][0] = Bs[buf][ks2 + t][c];
                b[nf][1] = Bs[buf][ks2 + t + 4][c];
            }
#pragma unroll
            for (int mf = 0; mf < 2; mf++)
#pragma unroll
                for (int nf = 0; nf < 4; nf++)
                    mma_f16(acc[mf][nf], a[mf], b[nf]);
        }
        __syncthreads();
    }

#pragma unroll
    for (int mf = 0; mf < 2; mf++) {
#pragma unroll
        for (int nf = 0; nf < 4; nf++) {
            int row0 = m0 + wm + mf * 16 + g;
            int col0 = n0 + wn + nf * 8 + 2 * t;   // even
#pragma unroll
            for (int rr = 0; rr < 2; rr++) {
                int row = row0 + rr * 8;
                if (row >= M) continue;
                float v0 = acc[mf][nf][rr * 2 + 0];
                float v1 = acc[mf][nf][rr * 2 + 1];
                if (MODE == 0) {
                    __half* C = (__half*)(blockIdx.z == 0 ? C0 : C1);
                    *reinterpret_cast<__half2*>(C + (long)row * N + col0) =
                        __floats2half2_rn(v0, v1);
                } else {
                    if (blockIdx.z == 0) {
                        float* cp = (float*)C0 + (long)row * N + col0;
                        if (col0 < N)     cp[0] = v0;
                        if (col0 + 1 < N) cp[1] = v1;
                    } else {
                        __half* cp = (__half*)C1 + (long)row * N + col0;
                        if (col0 < N)     cp[0] = __float2half(v0);
                        if (col0 + 1 < N) cp[1] = __float2half(v1);
                    }
                }
            }
        }
    }
}

// ---------------------------------------------------------------------------
// layer-0 gather + finalize: 2 nodes per warp, 16 lanes per node, uint4 rows.
// ---------------------------------------------------------------------------
__global__ void __launch_bounds__(256)
gather0_kernel(const float* __restrict__ b0) {
    __shared__ int sbk[16][CAP];
    int slot = threadIdx.x >> 4;               // 0..15
    int node = blockIdx.x * 16 + slot;         // NN = 3125*16 exactly
    int hl = threadIdx.x & 15;                 // half-lane 0..15
    int deg = g_cnt[node];
    int dm = min(deg, CAP);
    const int* bk = g_bucket + (long)node * CAP;

    for (int j = hl; j < dm; j += 16) sbk[slot][j] = bk[j];
    __syncwarp();

    float2 a0 = make_float2(0.f, 0.f);
    float2 a1 = make_float2(0.f, 0.f);
    float2 a2 = make_float2(0.f, 0.f);
    float2 a3 = make_float2(0.f, 0.f);
    int e = 0;
    for (; e + 1 < dm; e += 2) {
        int s0 = sbk[slot][e];
        int s1 = sbk[slot][e + 1];
        uint4 u0 = *reinterpret_cast<const uint4*>(g_Y0h + (long)s0 * F1 + hl * 8);
        uint4 u1 = *reinterpret_cast<const uint4*>(g_Y0h + (long)s1 * F1 + hl * 8);
        __half2 p0 = __hadd2(*reinterpret_cast<__half2*>(&u0.x), *reinterpret_cast<__half2*>(&u1.x));
        __half2 p1 = __hadd2(*reinterpret_cast<__half2*>(&u0.y), *reinterpret_cast<__half2*>(&u1.y));
        __half2 p2 = __hadd2(*reinterpret_cast<__half2*>(&u0.z), *reinterpret_cast<__half2*>(&u1.z));
        __half2 p3 = __hadd2(*reinterpret_cast<__half2*>(&u0.w), *reinterpret_cast<__half2*>(&u1.w));
        float2 f0 = __half22float2(p0);
        float2 f1 = __half22float2(p1);
        float2 f2 = __half22float2(p2);
        float2 f3 = __half22float2(p3);
        a0.x += f0.x; a0.y += f0.y;
        a1.x += f1.x; a1.y += f1.y;
        a2.x += f2.x; a2.y += f2.y;
        a3.x += f3.x; a3.y += f3.y;
    }
    if (e < dm) {
        int s0 = sbk[slot][e];
        uint4 u0 = *reinterpret_cast<const uint4*>(g_Y0h + (long)s0 * F1 + hl * 8);
        float2 f0 = __half22float2(*reinterpret_cast<__half2*>(&u0.x));
        float2 f1 = __half22float2(*reinterpret_cast<__half2*>(&u0.y));
        float2 f2 = __half22float2(*reinterpret_cast<__half2*>(&u0.z));
        float2 f3 = __half22float2(*reinterpret_cast<__half2*>(&u0.w));
        a0.x += f0.x; a0.y += f0.y;
        a1.x += f1.x; a1.y += f1.y;
        a2.x += f2.x; a2.y += f2.y;
        a3.x += f3.x; a3.y += f3.y;
    }

    float invd = 1.0f / fmaxf((float)deg, 1.0f);
    uint4 us = *reinterpret_cast<const uint4*>(g_S0h + (long)node * F1 + hl * 8);
    float2 s0f = __half22float2(*reinterpret_cast<__half2*>(&us.x));
    float2 s1f = __half22float2(*reinterpret_cast<__half2*>(&us.y));
    float2 s2f = __half22float2(*reinterpret_cast<__half2*>(&us.z));
    float2 s3f = __half22float2(*reinterpret_cast<__half2*>(&us.w));
    float4 bA = *reinterpret_cast<const float4*>(b0 + hl * 8);
    float4 bB = *reinterpret_cast<const float4*>(b0 + hl * 8 + 4);

    uint4 o;
    o.x = pack_h2(fmaxf(s0f.x + a0.x * invd + bA.x, 0.f),
                  fmaxf(s0f.y + a0.y * invd + bA.y, 0.f));
    o.y = pack_h2(fmaxf(s1f.x + a1.x * invd + bA.z, 0.f),
                  fmaxf(s1f.y + a1.y * invd + bA.w, 0.f));
    o.z = pack_h2(fmaxf(s2f.x + a2.x * invd + bB.x, 0.f),
                  fmaxf(s2f.y + a2.y * invd + bB.y, 0.f));
    o.w = pack_h2(fmaxf(s3f.x + a3.x * invd + bB.z, 0.f),
                  fmaxf(s3f.y + a3.y * invd + bB.w, 0.f));
    *reinterpret_cast<uint4*>(g_hh + (long)node * F1 + hl * 8) = o;
}

// ---------------------------------------------------------------------------
// layer-1 gather + finalize; smem bucket staging; restores g_cnt invariant.
// ---------------------------------------------------------------------------
__global__ void __launch_bounds__(256)
gather1_kernel(float* __restrict__ out, const float* __restrict__ b1) {
    __shared__ int sbk[8][CAP];
    int node = (blockIdx.x * blockDim.x + threadIdx.x) >> 5;
    if (node >= NN) return;
    int lane = threadIdx.x & 31;
    int wslot = (threadIdx.x >> 5) & 7;
    int deg = g_cnt[node];
    int dm = min(deg, CAP);
    const int* bk = g_bucket + (long)node * CAP;
    bool hi = (lane < NC - 32);

    for (int j = lane; j < dm; j += 32) sbk[wslot][j] = bk[j];
    __syncwarp();

    float acc0 = 0.f, acc1 = 0.f;
    for (int e = 0; e < dm; e++) {
        const __half* r0 = g_Y1h + (long)sbk[wslot][e] * NC;
        acc0 += __half2float(r0[lane]);
        if (hi) acc1 += __half2float(r0[lane + 32]);
    }

    float invd = 1.0f / fmaxf((float)deg, 1.0f);
    float* o = out + (long)node * NC;
    o[lane] = o[lane] + acc0 * invd + b1[lane];
    if (hi) o[lane + 32] = o[lane + 32] + acc1 * invd + b1[lane + 32];

    if (lane == 0) g_cnt[node] = 0;
}

// ---------------------------------------------------------------------------
extern "C" void kernel_launch(void* const* d_in, const int* in_sizes, int n_in,
                              void* d_out, int out_size) {
    const float* x        = (const float*)d_in[0];
    const int*   src      = (const int*)d_in[1];
    const int*   dst      = (const int*)d_in[2];
    const float* W_self0  = (const float*)d_in[3];
    const float* W_neigh0 = (const float*)d_in[4];
    const float* b0       = (const float*)d_in[5];
    const float* W_self1  = (const float*)d_in[6];
    const float* W_neigh1 = (const float*)d_in[7];
    const float* b1       = (const float*)d_in[8];
    float* out = (float*)d_out;

    const int M = in_sizes[0] / F0;   // 50000
    const int E = in_sizes[1];        // 800000

    __half* dXH;  cudaGetSymbolAddress((void**)&dXH,  g_xh);
    __half* dY0h; cudaGetSymbolAddress((void**)&dY0h, g_Y0h);
    __half* dS0h; cudaGetSymbolAddress((void**)&dS0h, g_S0h);
    __half* dY1h; cudaGetSymbolAddress((void**)&dY1h, g_Y1h);
    __half* dHH;  cudaGetSymbolAddress((void**)&dHH,  g_hh);
    uint32_t* dW0s; cudaGetSymbolAddress((void**)&dW0s, g_W0s);
    uint32_t* dW0n; cudaGetSymbolAddress((void**)&dW0n, g_W0n);
    uint32_t* dW1s; cudaGetSymbolAddress((void**)&dW1s, g_W1s);
    uint32_t* dW1n; cudaGetSymbolAddress((void**)&dW1n, g_W1n);

    cudaStream_t s_csr;
    cudaStreamCreateWithFlags(&s_csr, cudaStreamNonBlocking);
    cudaEvent_t ev_fork, ev_join;
    cudaEventCreateWithFlags(&ev_fork, cudaEventDisableTiming);
    cudaEventCreateWithFlags(&ev_join, cudaEventDisableTiming);

    // fork: bucket fill on side stream (overlaps cvt + GEMM0)
    cudaEventRecord(ev_fork, 0);
    cudaStreamWaitEvent(s_csr, ev_fork, 0);
    fill_kernel<<<(E / 2 + 255) / 256, 256, 0, s_csr>>>(src, dst, E);
    cudaEventRecord(ev_join, s_csr);

    // main stream: conversions, then layer-0 GEMM (pure fp16)
    cvt_x_kernel<<<(M * F0 / 8 + 255) / 256, 256>>>(x);
    cvt_w_kernel<<<(64 * 128 + 255) / 256, 256>>>(W_self0, W_neigh0, W_self1, W_neigh1);

    dim3 thr(256);
    dim3 g0((M + 127) / 128, F1 / 64, 2);   // (391, 2, 2)
    hgemm_f16_kernel<0><<<g0, thr>>>(dXH, dW0s, dW0n, dS0h, dY0h, M, F1, 128);

    // join: gather0 needs fill
    cudaStreamWaitEvent(0, ev_join, 0);
    gather0_kernel<<<NN / 16, 256>>>(b0);

    // layer 1: z=0 -> out (fp32), z=1 -> Y1h (fp16)
    dim3 g1((M + 127) / 128, 1, 2);
    hgemm_f16_kernel<1><<<g1, thr>>>(dHH, dW1s, dW1n, out, dY1h, M, NC, 64);

    gather1_kernel<<<(NN * 32 + 255) / 256, 256>>>(out, b1);

    cudaEventDestroy(ev_fork);
    cudaEventDestroy(ev_join);
    cudaStreamDestroy(s_csr);
}